// round 4
// baseline (speedup 1.0000x reference)
#include <cuda_runtime.h>

#define BB 4
#define KK 128
#define NPTS 50000
#define GD 128
#define TPB 256
#define CHUNKS ((NPTS + TPB - 1) / TPB)   // 196

// Per-Gaussian packed params: 5 float4 each
//  p0 = (cx, cy, cz, inv2s2)
//  p1 = (r00, r01, r02, logc2)
//  p2 = (r10, r11, r12, ctx)
//  p3 = (r20, r21, r22, cty)
//  p4 = (ctz, 0, 0, 0)
__device__ float4 g_params[BB * KK * 5];
__device__ float  g_partials[BB * CHUNKS];

__global__ void precompute_kernel(const float* __restrict__ constants,
                                  const float* __restrict__ scales,
                                  const float* __restrict__ rotations,
                                  const float* __restrict__ centers)
{
    int tid = blockIdx.x * blockDim.x + threadIdx.x;
    if (tid >= BB * KK) return;
    int b = tid / KK;
    int k = tid % KK;
    int bn = (b + 1) % BB;

    // R (this batch) and Rt (next batch), row-major 3x3
    float R[3][3], Rn[3][3];
    const float* rp  = rotations + ((size_t)b  * KK + k) * 9;
    const float* rpn = rotations + ((size_t)bn * KK + k) * 9;
#pragma unroll
    for (int i = 0; i < 3; i++)
#pragma unroll
        for (int j = 0; j < 3; j++) {
            R[i][j]  = rp[i * 3 + j];
            Rn[i][j] = rpn[i * 3 + j];
        }
    // R_rel[i][l] = sum_j Rn[i][j] * R[l][j]
    float Rr[3][3];
#pragma unroll
    for (int i = 0; i < 3; i++)
#pragma unroll
        for (int l = 0; l < 3; l++)
            Rr[i][l] = Rn[i][0] * R[l][0] + Rn[i][1] * R[l][1] + Rn[i][2] * R[l][2];

    float cx = centers[((size_t)b * KK + k) * 3 + 0];
    float cy = centers[((size_t)b * KK + k) * 3 + 1];
    float cz = centers[((size_t)b * KK + k) * 3 + 2];
    float ctx = centers[((size_t)bn * KK + k) * 3 + 0];
    float cty = centers[((size_t)bn * KK + k) * 3 + 1];
    float ctz = centers[((size_t)bn * KK + k) * 3 + 2];

    float s = scales[(size_t)b * KK + k];
    float c = constants[(size_t)b * KK + k];
    float inv2s2 = 1.0f / (2.0f * s * s);
    float logc2  = logf(c * c);

    float4* dst = g_params + (size_t)(b * KK + k) * 5;
    dst[0] = make_float4(cx, cy, cz, inv2s2);
    dst[1] = make_float4(Rr[0][0], Rr[0][1], Rr[0][2], logc2);
    dst[2] = make_float4(Rr[1][0], Rr[1][1], Rr[1][2], ctx);
    dst[3] = make_float4(Rr[2][0], Rr[2][1], Rr[2][2], cty);
    dst[4] = make_float4(ctz, 0.0f, 0.0f, 0.0f);
}

__global__ __launch_bounds__(TPB) void points_kernel(
    const float* __restrict__ samples,   // (B, N, 6)
    const float* __restrict__ grid,      // (B, GD, GD, GD)
    const float* __restrict__ w2g)       // (B, 4, 4)
{
    __shared__ float4 sP[KK * 5];

    const int b     = blockIdx.y;
    const int bn    = (b + 1) % BB;
    const int chunk = blockIdx.x;
    const int tid   = threadIdx.x;

    // Stage Gaussian params for this batch into shared
    const float4* src = g_params + (size_t)b * KK * 5;
    for (int i = tid; i < KK * 5; i += TPB) sP[i] = src[i];
    __syncthreads();

    const int n = chunk * TPB + tid;
    float local = 0.0f;

    if (n < NPTS) {
        const float* sp = samples + ((size_t)b * NPTS + n) * 6;
        const float px = sp[0], py = sp[1], pz = sp[2];

        float ax = 0.0f, ay = 0.0f, az = 0.0f, ws = 0.0f;

#pragma unroll 4
        for (int k = 0; k < KK; k++) {
            const float4 p0 = sP[k * 5 + 0];
            const float4 p1 = sP[k * 5 + 1];
            const float4 p2 = sP[k * 5 + 2];
            const float4 p3 = sP[k * 5 + 3];
            const float4 p4 = sP[k * 5 + 4];

            const float dx = px - p0.x;
            const float dy = py - p0.y;
            const float dz = pz - p0.z;
            const float d2 = dx * dx + dy * dy + dz * dz;
            const float w  = __expf(p1.w - d2 * p0.w);

            const float tx = p2.w + p1.x * dx + p1.y * dy + p1.z * dz;
            const float ty = p3.w + p2.x * dx + p2.y * dy + p2.z * dz;
            const float tz = p4.x + p3.x * dx + p3.y * dy + p3.z * dz;

            ax += w * tx;
            ay += w * ty;
            az += w * tz;
            ws += w;
        }

        const float inv = 1.0f / ws;
        const float bx = ax * inv, by = ay * inv, bz = az * inv;

        // world2grid of NEXT batch (rolled)
        const float* A = w2g + (size_t)bn * 16;
        float gx = A[0]  * bx + A[1]  * by + A[2]  * bz + A[3];
        float gy = A[4]  * bx + A[5]  * by + A[6]  * bz + A[7];
        float gz = A[8]  * bx + A[9]  * by + A[10] * bz + A[11];

        // gcs = 2*(gc/denom) - 1; then x = clip((gcs+1)*0.5*(dim-1), 0, dim-1)
        const float dm = (float)(GD - 1);
        float ncx = 2.0f * (gx / dm) - 1.0f;
        float ncy = 2.0f * (gy / dm) - 1.0f;
        float ncz = 2.0f * (gz / dm) - 1.0f;

        float x = fminf(fmaxf((ncx + 1.0f) * 0.5f * dm, 0.0f), dm);
        float y = fminf(fmaxf((ncy + 1.0f) * 0.5f * dm, 0.0f), dm);
        float z = fminf(fmaxf((ncz + 1.0f) * 0.5f * dm, 0.0f), dm);

        float x0f = floorf(x), y0f = floorf(y), z0f = floorf(z);
        float fx = x - x0f, fy = y - y0f, fz = z - z0f;
        int x0 = (int)x0f, y0 = (int)y0f, z0 = (int)z0f;
        int x1 = min(x0 + 1, GD - 1);
        int y1 = min(y0 + 1, GD - 1);
        int z1 = min(z0 + 1, GD - 1);

        const float* vol = grid + (size_t)bn * GD * GD * GD;
        const int sz = GD * GD;
        int b00 = z0 * sz + y0 * GD;
        int b01 = z0 * sz + y1 * GD;
        int b10 = z1 * sz + y0 * GD;
        int b11 = z1 * sz + y1 * GD;

        float c000 = __ldg(vol + b00 + x0);
        float c001 = __ldg(vol + b00 + x1);
        float c010 = __ldg(vol + b01 + x0);
        float c011 = __ldg(vol + b01 + x1);
        float c100 = __ldg(vol + b10 + x0);
        float c101 = __ldg(vol + b10 + x1);
        float c110 = __ldg(vol + b11 + x0);
        float c111 = __ldg(vol + b11 + x1);

        float c00 = c000 + (c001 - c000) * fx;
        float c01 = c010 + (c011 - c010) * fx;
        float c10 = c100 + (c101 - c100) * fx;
        float c11 = c110 + (c111 - c110) * fx;
        float c0  = c00 + (c01 - c00) * fy;
        float c1  = c10 + (c11 - c10) * fy;
        float sdf = c0 + (c1 - c0) * fz;

        local = sdf * sdf;
    }

    // Block reduction (deterministic)
    __shared__ float red[TPB / 32];
    float v = local;
#pragma unroll
    for (int off = 16; off > 0; off >>= 1)
        v += __shfl_down_sync(0xFFFFFFFFu, v, off);
    const int lane = tid & 31;
    const int warp = tid >> 5;
    if (lane == 0) red[warp] = v;
    __syncthreads();
    if (warp == 0) {
        v = (lane < TPB / 32) ? red[lane] : 0.0f;
#pragma unroll
        for (int off = 4; off > 0; off >>= 1)
            v += __shfl_down_sync(0xFFFFFFFFu, v, off);
        if (lane == 0) g_partials[b * CHUNKS + chunk] = v;
    }
}

__global__ void reduce_kernel(float* __restrict__ out)
{
    const int tid = threadIdx.x;
    float v = 0.0f;
    for (int i = tid; i < BB * CHUNKS; i += 256) v += g_partials[i];
    __shared__ float red[8];
#pragma unroll
    for (int off = 16; off > 0; off >>= 1)
        v += __shfl_down_sync(0xFFFFFFFFu, v, off);
    const int lane = tid & 31;
    const int warp = tid >> 5;
    if (lane == 0) red[warp] = v;
    __syncthreads();
    if (warp == 0) {
        v = (lane < 8) ? red[lane] : 0.0f;
#pragma unroll
        for (int off = 4; off > 0; off >>= 1)
            v += __shfl_down_sync(0xFFFFFFFFu, v, off);
        if (lane == 0) out[0] = v / (float)NPTS;
    }
}

extern "C" void kernel_launch(void* const* d_in, const int* in_sizes, int n_in,
                              void* d_out, int out_size)
{
    const float* constants = (const float*)d_in[0]; // (B,K)
    const float* scales    = (const float*)d_in[1]; // (B,K)
    const float* rotations = (const float*)d_in[2]; // (B,K,3,3)
    const float* centers   = (const float*)d_in[3]; // (B,K,3)
    const float* samples   = (const float*)d_in[4]; // (B,N,6)
    const float* grid      = (const float*)d_in[5]; // (B,GD,GD,GD)
    const float* w2g       = (const float*)d_in[6]; // (B,4,4)
    float* out = (float*)d_out;

    precompute_kernel<<<2, 256>>>(constants, scales, rotations, centers);
    dim3 g(CHUNKS, BB);
    points_kernel<<<g, TPB>>>(samples, grid, w2g);
    reduce_kernel<<<1, 256>>>(out);
}

// round 7
// speedup vs baseline: 1.2439x; 1.2439x over previous
#include <cuda_runtime.h>

#define BB 4
#define KK 128
#define NPTS 50000
#define GD 128
#define TPB 256
#define PPB 512                           // points per block (2 per thread)
#define CHUNKS ((NPTS + PPB - 1) / PPB)   // 98
#define NBLK (CHUNKS * BB)                // 392

typedef unsigned long long u64;

__device__ float        g_partials[NBLK];
__device__ unsigned int g_count = 0;

// ---- packed f32x2 helpers ----
__device__ __forceinline__ u64 pk2(float lo, float hi) {
    u64 r; asm("mov.b64 %0, {%1, %2};" : "=l"(r) : "f"(lo), "f"(hi)); return r;
}
__device__ __forceinline__ void upk2(float& lo, float& hi, u64 v) {
    asm("mov.b64 {%0, %1}, %2;" : "=f"(lo), "=f"(hi) : "l"(v));
}
#define F2FMA(d,a,b,c) asm("fma.rn.f32x2 %0, %1, %2, %3;" : "=l"(d) : "l"(a), "l"(b), "l"(c))
#define F2ADD(d,a,b)   asm("add.rn.f32x2 %0, %1, %2;"     : "=l"(d) : "l"(a), "l"(b))
#define F2MUL(d,a,b)   asm("mul.rn.f32x2 %0, %1, %2;"     : "=l"(d) : "l"(a), "l"(b))

__device__ __forceinline__ float ex2f(float x) {
    float r; asm("ex2.approx.ftz.f32 %0, %1;" : "=f"(r) : "f"(x)); return r;
}

// world -> grid -> normalized -> grid round trip + trilinear border sample
__device__ __forceinline__ float sample_sdf(const float* __restrict__ vol,
                                            const float* __restrict__ A,
                                            float bx, float by, float bz)
{
    float gx = A[0] * bx + A[1] * by + A[2]  * bz + A[3];
    float gy = A[4] * bx + A[5] * by + A[6]  * bz + A[7];
    float gz = A[8] * bx + A[9] * by + A[10] * bz + A[11];

    const float dm = (float)(GD - 1);
    float ncx = 2.0f * (gx / dm) - 1.0f;
    float ncy = 2.0f * (gy / dm) - 1.0f;
    float ncz = 2.0f * (gz / dm) - 1.0f;

    float x = fminf(fmaxf((ncx + 1.0f) * 0.5f * dm, 0.0f), dm);
    float y = fminf(fmaxf((ncy + 1.0f) * 0.5f * dm, 0.0f), dm);
    float z = fminf(fmaxf((ncz + 1.0f) * 0.5f * dm, 0.0f), dm);

    float x0f = floorf(x), y0f = floorf(y), z0f = floorf(z);
    float fx = x - x0f, fy = y - y0f, fz = z - z0f;
    int x0 = (int)x0f, y0 = (int)y0f, z0 = (int)z0f;
    int x1 = min(x0 + 1, GD - 1);
    int y1 = min(y0 + 1, GD - 1);
    int z1 = min(z0 + 1, GD - 1);

    const int sz = GD * GD;
    int b00 = z0 * sz + y0 * GD;
    int b01 = z0 * sz + y1 * GD;
    int b10 = z1 * sz + y0 * GD;
    int b11 = z1 * sz + y1 * GD;

    float c000 = __ldg(vol + b00 + x0);
    float c001 = __ldg(vol + b00 + x1);
    float c010 = __ldg(vol + b01 + x0);
    float c011 = __ldg(vol + b01 + x1);
    float c100 = __ldg(vol + b10 + x0);
    float c101 = __ldg(vol + b10 + x1);
    float c110 = __ldg(vol + b11 + x0);
    float c111 = __ldg(vol + b11 + x1);

    float c00 = c000 + (c001 - c000) * fx;
    float c01 = c010 + (c011 - c010) * fx;
    float c10 = c100 + (c101 - c100) * fx;
    float c11 = c110 + (c111 - c110) * fx;
    float c0  = c00 + (c01 - c00) * fy;
    float c1  = c10 + (c11 - c10) * fy;
    return c0 + (c1 - c0) * fz;
}

// Per-k duplicated param layout (18 u64 = 144B, 16B aligned):
//  0:(-cx,-cx) 1:(-cy,-cy) 2:(-cz,-cz) 3:(ni,ni) 4:(lc,lc)
//  5..13: r00..r22 dup   14:(ctx) 15:(cty) 16:(ctz) 17:pad
__global__ __launch_bounds__(TPB) void fused_kernel(
    const float* __restrict__ constants,
    const float* __restrict__ scales,
    const float* __restrict__ rotations,
    const float* __restrict__ centers,
    const float* __restrict__ samples,
    const float* __restrict__ grid,
    const float* __restrict__ w2g,
    float* __restrict__ out)
{
    __shared__ __align__(16) u64 sParams[KK * 18];
    __shared__ float sRed[TPB / 32];
    __shared__ int   sLast;

    const int b     = blockIdx.y;
    const int bn    = (b + 1) % BB;
    const int chunk = blockIdx.x;
    const int tid   = threadIdx.x;

    // ---- prologue: per-block param precompute (threads 0..127, one k each) ----
    if (tid < KK) {
        const int k = tid;
        float R[3][3], Rn[3][3];
        const float* rp  = rotations + ((size_t)b  * KK + k) * 9;
        const float* rpn = rotations + ((size_t)bn * KK + k) * 9;
#pragma unroll
        for (int i = 0; i < 3; i++)
#pragma unroll
            for (int j = 0; j < 3; j++) {
                R[i][j]  = __ldg(rp  + i * 3 + j);
                Rn[i][j] = __ldg(rpn + i * 3 + j);
            }
        float Rr[3][3];
#pragma unroll
        for (int i = 0; i < 3; i++)
#pragma unroll
            for (int l = 0; l < 3; l++)
                Rr[i][l] = Rn[i][0] * R[l][0] + Rn[i][1] * R[l][1] + Rn[i][2] * R[l][2];

        const float cx  = __ldg(centers + ((size_t)b  * KK + k) * 3 + 0);
        const float cy  = __ldg(centers + ((size_t)b  * KK + k) * 3 + 1);
        const float cz  = __ldg(centers + ((size_t)b  * KK + k) * 3 + 2);
        const float ctx = __ldg(centers + ((size_t)bn * KK + k) * 3 + 0);
        const float cty = __ldg(centers + ((size_t)bn * KK + k) * 3 + 1);
        const float ctz = __ldg(centers + ((size_t)bn * KK + k) * 3 + 2);

        const float s = __ldg(scales    + (size_t)b * KK + k);
        const float c = __ldg(constants + (size_t)b * KK + k);
        const float LOG2E = 1.4426950408889634f;
        const float ni = -(1.0f / (2.0f * s * s)) * LOG2E;   // ex2 domain
        const float lc = __log2f(c * c);                      // log2(c^2)

        u64* d = sParams + k * 18;
        d[0]  = pk2(-cx, -cx);
        d[1]  = pk2(-cy, -cy);
        d[2]  = pk2(-cz, -cz);
        d[3]  = pk2(ni, ni);
        d[4]  = pk2(lc, lc);
        d[5]  = pk2(Rr[0][0], Rr[0][0]);
        d[6]  = pk2(Rr[0][1], Rr[0][1]);
        d[7]  = pk2(Rr[0][2], Rr[0][2]);
        d[8]  = pk2(Rr[1][0], Rr[1][0]);
        d[9]  = pk2(Rr[1][1], Rr[1][1]);
        d[10] = pk2(Rr[1][2], Rr[1][2]);
        d[11] = pk2(Rr[2][0], Rr[2][0]);
        d[12] = pk2(Rr[2][1], Rr[2][1]);
        d[13] = pk2(Rr[2][2], Rr[2][2]);
        d[14] = pk2(ctx, ctx);
        d[15] = pk2(cty, cty);
        d[16] = pk2(ctz, ctz);
        d[17] = 0ULL;
    }
    __syncthreads();

    // ---- load the two points of this thread ----
    const int nA = chunk * PPB + tid;            // always < NPTS for this shape
    const int nB = nA + TPB;
    const bool validB = (nB < NPTS);

    const float* spA = samples + ((size_t)b * NPTS + nA) * 6;
    float px0 = spA[0], py0 = spA[1], pz0 = spA[2];
    float px1 = 0.0f, py1 = 0.0f, pz1 = 0.0f;
    if (validB) {
        const float* spB = samples + ((size_t)b * NPTS + nB) * 6;
        px1 = spB[0]; py1 = spB[1]; pz1 = spB[2];
    }
    const u64 pxp = pk2(px0, px1);
    const u64 pyp = pk2(py0, py1);
    const u64 pzp = pk2(pz0, pz1);

    u64 ax = 0ULL, ay = 0ULL, az = 0ULL, ws = 0ULL;  // packed (0.0f,0.0f)

    const ulonglong2* __restrict__ sq = (const ulonglong2*)sParams;

    // ---- main loop: packed f32x2 over K=128 gaussians ----
#pragma unroll 2
    for (int k = 0; k < KK; k++) {
        const ulonglong2 j0 = sq[0];   // (-cx,-cy)
        const ulonglong2 j1 = sq[1];   // (-cz, ni)
        u64 dx; F2ADD(dx, pxp, j0.x);
        u64 dy; F2ADD(dy, pyp, j0.y);
        u64 dz; F2ADD(dz, pzp, j1.x);

        u64 t;  F2MUL(t, dz, dz);
        F2FMA(t, dy, dy, t);
        F2FMA(t, dx, dx, t);

        const ulonglong2 j2 = sq[2];   // (lc, r00)
        u64 arg; F2FMA(arg, t, j1.y, j2.x);
        float a0, a1; upk2(a0, a1, arg);
        const u64 w = pk2(ex2f(a0), ex2f(a1));

        const ulonglong2 j3 = sq[3];   // (r01, r02)
        const ulonglong2 j4 = sq[4];   // (r10, r11)
        const ulonglong2 j5 = sq[5];   // (r12, r20)
        const ulonglong2 j6 = sq[6];   // (r21, r22)
        const ulonglong2 j7 = sq[7];   // (ctx, cty)
        const ulonglong2 j8 = sq[8];   // (ctz, pad)

        u64 tx; F2FMA(tx, j3.y, dz, j7.x);
        F2FMA(tx, j3.x, dy, tx);
        F2FMA(tx, j2.y, dx, tx);

        u64 ty; F2FMA(ty, j5.x, dz, j7.y);
        F2FMA(ty, j4.y, dy, ty);
        F2FMA(ty, j4.x, dx, ty);

        u64 tz; F2FMA(tz, j6.y, dz, j8.x);
        F2FMA(tz, j6.x, dy, tz);
        F2FMA(tz, j5.y, dx, tz);

        F2FMA(ax, w, tx, ax);
        F2FMA(ay, w, ty, ay);
        F2FMA(az, w, tz, az);
        F2ADD(ws, ws, w);

        sq += 9;
    }

    // ---- epilogue: normalize, transform, trilinear sample, square ----
    float ax0, ax1, ay0, ay1, az0, az1, ws0, ws1;
    upk2(ax0, ax1, ax);
    upk2(ay0, ay1, ay);
    upk2(az0, az1, az);
    upk2(ws0, ws1, ws);

    const float* A   = w2g + (size_t)bn * 16;
    const float* vol = grid + (size_t)bn * GD * GD * GD;

    float local;
    {
        const float inv = 1.0f / ws0;
        const float s0 = sample_sdf(vol, A, ax0 * inv, ay0 * inv, az0 * inv);
        local = s0 * s0;
    }
    if (validB) {
        const float inv = 1.0f / ws1;
        const float s1 = sample_sdf(vol, A, ax1 * inv, ay1 * inv, az1 * inv);
        local += s1 * s1;
    }

    // ---- block reduction (deterministic) ----
    float v = local;
#pragma unroll
    for (int off = 16; off > 0; off >>= 1)
        v += __shfl_down_sync(0xFFFFFFFFu, v, off);
    const int lane = tid & 31;
    const int warp = tid >> 5;
    if (lane == 0) sRed[warp] = v;
    __syncthreads();
    if (warp == 0) {
        v = (lane < TPB / 32) ? sRed[lane] : 0.0f;
#pragma unroll
        for (int off = 4; off > 0; off >>= 1)
            v += __shfl_down_sync(0xFFFFFFFFu, v, off);
        if (lane == 0) g_partials[b * CHUNKS + chunk] = v;
    }
    __syncthreads();

    // ---- last block reduces all partials (graph-replay-safe counter) ----
    if (tid == 0) {
        __threadfence();
        unsigned int prev = atomicAdd(&g_count, 1u);
        sLast = (prev == (unsigned int)(NBLK - 1)) ? 1 : 0;
    }
    __syncthreads();

    if (sLast) {
        float r = 0.0f;
        for (int i = tid; i < NBLK; i += TPB) r += g_partials[i];
#pragma unroll
        for (int off = 16; off > 0; off >>= 1)
            r += __shfl_down_sync(0xFFFFFFFFu, r, off);
        if (lane == 0) sRed[warp] = r;
        __syncthreads();
        if (warp == 0) {
            r = (lane < TPB / 32) ? sRed[lane] : 0.0f;
#pragma unroll
            for (int off = 4; off > 0; off >>= 1)
                r += __shfl_down_sync(0xFFFFFFFFu, r, off);
            if (lane == 0) {
                out[0] = r / (float)NPTS;
                g_count = 0u;   // self-reset for next graph replay
            }
        }
    }
}

extern "C" void kernel_launch(void* const* d_in, const int* in_sizes, int n_in,
                              void* d_out, int out_size)
{
    const float* constants = (const float*)d_in[0]; // (B,K)
    const float* scales    = (const float*)d_in[1]; // (B,K)
    const float* rotations = (const float*)d_in[2]; // (B,K,3,3)
    const float* centers   = (const float*)d_in[3]; // (B,K,3)
    const float* samples   = (const float*)d_in[4]; // (B,N,6)
    const float* grid      = (const float*)d_in[5]; // (B,GD,GD,GD)
    const float* w2g       = (const float*)d_in[6]; // (B,4,4)
    float* out = (float*)d_out;

    dim3 g(CHUNKS, BB);
    fused_kernel<<<g, TPB>>>(constants, scales, rotations, centers,
                             samples, grid, w2g, out);
}

// round 10
// speedup vs baseline: 1.3364x; 1.0743x over previous
#include <cuda_runtime.h>

#define BB 4
#define KK 128
#define NPTS 50000
#define GD 128
#define TPB 128
#define PPB 512                           // points per block (4 per thread)
#define CHUNKS ((NPTS + PPB - 1) / PPB)   // 98
#define NBLK (CHUNKS * BB)                // 392

typedef unsigned long long u64;

__device__ float        g_partials[NBLK];
__device__ unsigned int g_count = 0;

// ---- packed f32x2 helpers ----
__device__ __forceinline__ u64 pk2(float lo, float hi) {
    u64 r; asm("mov.b64 %0, {%1, %2};" : "=l"(r) : "f"(lo), "f"(hi)); return r;
}
__device__ __forceinline__ void upk2(float& lo, float& hi, u64 v) {
    asm("mov.b64 {%0, %1}, %2;" : "=f"(lo), "=f"(hi) : "l"(v));
}
#define F2FMA(d,a,b,c) asm("fma.rn.f32x2 %0, %1, %2, %3;" : "=l"(d) : "l"(a), "l"(b), "l"(c))
#define F2ADD(d,a,b)   asm("add.rn.f32x2 %0, %1, %2;"     : "=l"(d) : "l"(a), "l"(b))
#define F2MUL(d,a,b)   asm("mul.rn.f32x2 %0, %1, %2;"     : "=l"(d) : "l"(a), "l"(b))

__device__ __forceinline__ float ex2f(float x) {
    float r; asm("ex2.approx.ftz.f32 %0, %1;" : "=f"(r) : "f"(x)); return r;
}

// world -> grid -> normalized -> grid round trip + trilinear border sample
__device__ __forceinline__ float sample_sdf(const float* __restrict__ vol,
                                            const float* __restrict__ A,
                                            float bx, float by, float bz)
{
    float gx = A[0] * bx + A[1] * by + A[2]  * bz + A[3];
    float gy = A[4] * bx + A[5] * by + A[6]  * bz + A[7];
    float gz = A[8] * bx + A[9] * by + A[10] * bz + A[11];

    const float dm = (float)(GD - 1);
    float ncx = 2.0f * (gx / dm) - 1.0f;
    float ncy = 2.0f * (gy / dm) - 1.0f;
    float ncz = 2.0f * (gz / dm) - 1.0f;

    float x = fminf(fmaxf((ncx + 1.0f) * 0.5f * dm, 0.0f), dm);
    float y = fminf(fmaxf((ncy + 1.0f) * 0.5f * dm, 0.0f), dm);
    float z = fminf(fmaxf((ncz + 1.0f) * 0.5f * dm, 0.0f), dm);

    float x0f = floorf(x), y0f = floorf(y), z0f = floorf(z);
    float fx = x - x0f, fy = y - y0f, fz = z - z0f;
    int x0 = (int)x0f, y0 = (int)y0f, z0 = (int)z0f;
    int x1 = min(x0 + 1, GD - 1);
    int y1 = min(y0 + 1, GD - 1);
    int z1 = min(z0 + 1, GD - 1);

    const int sz = GD * GD;
    int b00 = z0 * sz + y0 * GD;
    int b01 = z0 * sz + y1 * GD;
    int b10 = z1 * sz + y0 * GD;
    int b11 = z1 * sz + y1 * GD;

    float c000 = __ldg(vol + b00 + x0);
    float c001 = __ldg(vol + b00 + x1);
    float c010 = __ldg(vol + b01 + x0);
    float c011 = __ldg(vol + b01 + x1);
    float c100 = __ldg(vol + b10 + x0);
    float c101 = __ldg(vol + b10 + x1);
    float c110 = __ldg(vol + b11 + x0);
    float c111 = __ldg(vol + b11 + x1);

    float c00 = c000 + (c001 - c000) * fx;
    float c01 = c010 + (c011 - c010) * fx;
    float c10 = c100 + (c101 - c100) * fx;
    float c11 = c110 + (c111 - c110) * fx;
    float c0  = c00 + (c01 - c00) * fy;
    float c1  = c10 + (c11 - c10) * fy;
    return c0 + (c1 - c0) * fz;
}

// One packed (2-point) stream for one gaussian k.
__device__ __forceinline__ void gauss_step(
    const ulonglong2 j0, const ulonglong2 j1, const ulonglong2 j2,
    const ulonglong2 j3, const ulonglong2 j4, const ulonglong2 j5,
    const ulonglong2 j6, const ulonglong2 j7, const ulonglong2 j8,
    u64 pxp, u64 pyp, u64 pzp,
    u64& ax, u64& ay, u64& az, u64& ws)
{
    u64 dx; F2ADD(dx, pxp, j0.x);
    u64 dy; F2ADD(dy, pyp, j0.y);
    u64 dz; F2ADD(dz, pzp, j1.x);

    u64 t;  F2MUL(t, dz, dz);
    F2FMA(t, dy, dy, t);
    F2FMA(t, dx, dx, t);

    u64 arg; F2FMA(arg, t, j1.y, j2.x);
    float a0, a1; upk2(a0, a1, arg);
    const u64 w = pk2(ex2f(a0), ex2f(a1));

    u64 tx; F2FMA(tx, j3.y, dz, j7.x);
    F2FMA(tx, j3.x, dy, tx);
    F2FMA(tx, j2.y, dx, tx);

    u64 ty; F2FMA(ty, j5.x, dz, j7.y);
    F2FMA(ty, j4.y, dy, ty);
    F2FMA(ty, j4.x, dx, ty);

    u64 tz; F2FMA(tz, j6.y, dz, j8.x);
    F2FMA(tz, j6.x, dy, tz);
    F2FMA(tz, j5.y, dx, tz);

    F2FMA(ax, w, tx, ax);
    F2FMA(ay, w, ty, ay);
    F2FMA(az, w, tz, az);
    F2ADD(ws, ws, w);
}

// Per-k duplicated param layout (18 u64 = 144B, 16B aligned):
//  j0=(-cx,-cy) j1=(-cz,ni) j2=(lc,r00) j3=(r01,r02) j4=(r10,r11)
//  j5=(r12,r20) j6=(r21,r22) j7=(ctx,cty) j8=(ctz,pad)   [each u64 = (v,v)]
__global__ __launch_bounds__(TPB) void fused_kernel(
    const float* __restrict__ constants,
    const float* __restrict__ scales,
    const float* __restrict__ rotations,
    const float* __restrict__ centers,
    const float* __restrict__ samples,
    const float* __restrict__ grid,
    const float* __restrict__ w2g,
    float* __restrict__ out)
{
    __shared__ __align__(16) u64 sParams[KK * 18];
    __shared__ float sRed[TPB / 32];
    __shared__ int   sLast;

    const int b     = blockIdx.y;
    const int bn    = (b + 1) % BB;
    const int chunk = blockIdx.x;
    const int tid   = threadIdx.x;

    // ---- prologue: per-block param precompute (one k per thread) ----
    {
        const int k = tid;   // TPB == KK
        float R[3][3], Rn[3][3];
        const float* rp  = rotations + ((size_t)b  * KK + k) * 9;
        const float* rpn = rotations + ((size_t)bn * KK + k) * 9;
#pragma unroll
        for (int i = 0; i < 3; i++)
#pragma unroll
            for (int j = 0; j < 3; j++) {
                R[i][j]  = __ldg(rp  + i * 3 + j);
                Rn[i][j] = __ldg(rpn + i * 3 + j);
            }
        float Rr[3][3];
#pragma unroll
        for (int i = 0; i < 3; i++)
#pragma unroll
            for (int l = 0; l < 3; l++)
                Rr[i][l] = Rn[i][0] * R[l][0] + Rn[i][1] * R[l][1] + Rn[i][2] * R[l][2];

        const float cx  = __ldg(centers + ((size_t)b  * KK + k) * 3 + 0);
        const float cy  = __ldg(centers + ((size_t)b  * KK + k) * 3 + 1);
        const float cz  = __ldg(centers + ((size_t)b  * KK + k) * 3 + 2);
        const float ctx = __ldg(centers + ((size_t)bn * KK + k) * 3 + 0);
        const float cty = __ldg(centers + ((size_t)bn * KK + k) * 3 + 1);
        const float ctz = __ldg(centers + ((size_t)bn * KK + k) * 3 + 2);

        const float s = __ldg(scales    + (size_t)b * KK + k);
        const float c = __ldg(constants + (size_t)b * KK + k);
        const float LOG2E = 1.4426950408889634f;
        const float ni = -(1.0f / (2.0f * s * s)) * LOG2E;   // ex2 domain
        const float lc = __log2f(c * c);                      // log2(c^2)

        u64* d = sParams + k * 18;
        d[0]  = pk2(-cx, -cx);
        d[1]  = pk2(-cy, -cy);
        d[2]  = pk2(-cz, -cz);
        d[3]  = pk2(ni, ni);
        d[4]  = pk2(lc, lc);
        d[5]  = pk2(Rr[0][0], Rr[0][0]);
        d[6]  = pk2(Rr[0][1], Rr[0][1]);
        d[7]  = pk2(Rr[0][2], Rr[0][2]);
        d[8]  = pk2(Rr[1][0], Rr[1][0]);
        d[9]  = pk2(Rr[1][1], Rr[1][1]);
        d[10] = pk2(Rr[1][2], Rr[1][2]);
        d[11] = pk2(Rr[2][0], Rr[2][0]);
        d[12] = pk2(Rr[2][1], Rr[2][1]);
        d[13] = pk2(Rr[2][2], Rr[2][2]);
        d[14] = pk2(ctx, ctx);
        d[15] = pk2(cty, cty);
        d[16] = pk2(ctz, ctz);
        d[17] = 0ULL;
    }
    __syncthreads();

    // ---- load the four points of this thread ----
    const int n0 = chunk * PPB + tid;          // always < NPTS
    const int n1 = n0 + TPB;                   // always < NPTS (<= 49919)
    const int n2 = n0 + 2 * TPB;
    const int n3 = n0 + 3 * TPB;
    const bool v2 = (n2 < NPTS);
    const bool v3 = (n3 < NPTS);

    const float* base = samples + (size_t)b * NPTS * 6;
    float px0 = base[n0 * 6 + 0], py0 = base[n0 * 6 + 1], pz0 = base[n0 * 6 + 2];
    float px1 = base[n1 * 6 + 0], py1 = base[n1 * 6 + 1], pz1 = base[n1 * 6 + 2];
    float px2 = 0.f, py2 = 0.f, pz2 = 0.f;
    float px3 = 0.f, py3 = 0.f, pz3 = 0.f;
    if (v2) { px2 = base[n2 * 6 + 0]; py2 = base[n2 * 6 + 1]; pz2 = base[n2 * 6 + 2]; }
    if (v3) { px3 = base[n3 * 6 + 0]; py3 = base[n3 * 6 + 1]; pz3 = base[n3 * 6 + 2]; }

    const u64 pxA = pk2(px0, px1), pyA = pk2(py0, py1), pzA = pk2(pz0, pz1);
    const u64 pxB = pk2(px2, px3), pyB = pk2(py2, py3), pzB = pk2(pz2, pz3);

    u64 axA = 0ULL, ayA = 0ULL, azA = 0ULL, wsA = 0ULL;
    u64 axB = 0ULL, ayB = 0ULL, azB = 0ULL, wsB = 0ULL;

    const ulonglong2* __restrict__ sq = (const ulonglong2*)sParams;

    // ---- main loop: each 144B param load feeds 4 points (2 packed streams) ----
#pragma unroll 2
    for (int k = 0; k < KK; k++) {
        const ulonglong2 j0 = sq[0];
        const ulonglong2 j1 = sq[1];
        const ulonglong2 j2 = sq[2];
        const ulonglong2 j3 = sq[3];
        const ulonglong2 j4 = sq[4];
        const ulonglong2 j5 = sq[5];
        const ulonglong2 j6 = sq[6];
        const ulonglong2 j7 = sq[7];
        const ulonglong2 j8 = sq[8];

        gauss_step(j0, j1, j2, j3, j4, j5, j6, j7, j8,
                   pxA, pyA, pzA, axA, ayA, azA, wsA);
        gauss_step(j0, j1, j2, j3, j4, j5, j6, j7, j8,
                   pxB, pyB, pzB, axB, ayB, azB, wsB);

        sq += 9;
    }

    // ---- epilogue: normalize, transform, trilinear sample, square ----
    const float* A   = w2g + (size_t)bn * 16;
    const float* vol = grid + (size_t)bn * GD * GD * GD;

    float local = 0.0f;
    {
        float x0, x1, y0, y1, z0, z1, w0, w1;
        upk2(x0, x1, axA); upk2(y0, y1, ayA); upk2(z0, z1, azA); upk2(w0, w1, wsA);
        float inv = 1.0f / w0;
        float s0 = sample_sdf(vol, A, x0 * inv, y0 * inv, z0 * inv);
        local += s0 * s0;
        inv = 1.0f / w1;
        float s1 = sample_sdf(vol, A, x1 * inv, y1 * inv, z1 * inv);
        local += s1 * s1;
    }
    {
        float x0, x1, y0, y1, z0, z1, w0, w1;
        upk2(x0, x1, axB); upk2(y0, y1, ayB); upk2(z0, z1, azB); upk2(w0, w1, wsB);
        if (v2) {
            float inv = 1.0f / w0;
            float s0 = sample_sdf(vol, A, x0 * inv, y0 * inv, z0 * inv);
            local += s0 * s0;
        }
        if (v3) {
            float inv = 1.0f / w1;
            float s1 = sample_sdf(vol, A, x1 * inv, y1 * inv, z1 * inv);
            local += s1 * s1;
        }
    }

    // ---- block reduction (deterministic) ----
    float v = local;
#pragma unroll
    for (int off = 16; off > 0; off >>= 1)
        v += __shfl_down_sync(0xFFFFFFFFu, v, off);
    const int lane = tid & 31;
    const int warp = tid >> 5;
    if (lane == 0) sRed[warp] = v;
    __syncthreads();
    if (warp == 0) {
        v = (lane < TPB / 32) ? sRed[lane] : 0.0f;
#pragma unroll
        for (int off = 2; off > 0; off >>= 1)
            v += __shfl_down_sync(0xFFFFFFFFu, v, off);
        if (lane == 0) g_partials[b * CHUNKS + chunk] = v;
    }
    __syncthreads();

    // ---- last block reduces all partials (graph-replay-safe counter) ----
    if (tid == 0) {
        __threadfence();
        unsigned int prev = atomicAdd(&g_count, 1u);
        sLast = (prev == (unsigned int)(NBLK - 1)) ? 1 : 0;
    }
    __syncthreads();

    if (sLast) {
        float r = 0.0f;
        for (int i = tid; i < NBLK; i += TPB) r += g_partials[i];
#pragma unroll
        for (int off = 16; off > 0; off >>= 1)
            r += __shfl_down_sync(0xFFFFFFFFu, r, off);
        if (lane == 0) sRed[warp] = r;
        __syncthreads();
        if (warp == 0) {
            r = (lane < TPB / 32) ? sRed[lane] : 0.0f;
#pragma unroll
            for (int off = 2; off > 0; off >>= 1)
                r += __shfl_down_sync(0xFFFFFFFFu, r, off);
            if (lane == 0) {
                out[0] = r / (float)NPTS;
                g_count = 0u;   // self-reset for next graph replay
            }
        }
    }
}

extern "C" void kernel_launch(void* const* d_in, const int* in_sizes, int n_in,
                              void* d_out, int out_size)
{
    const float* constants = (const float*)d_in[0]; // (B,K)
    const float* scales    = (const float*)d_in[1]; // (B,K)
    const float* rotations = (const float*)d_in[2]; // (B,K,3,3)
    const float* centers   = (const float*)d_in[3]; // (B,K,3)
    const float* samples   = (const float*)d_in[4]; // (B,N,6)
    const float* grid      = (const float*)d_in[5]; // (B,GD,GD,GD)
    const float* w2g       = (const float*)d_in[6]; // (B,4,4)
    float* out = (float*)d_out;

    dim3 g(CHUNKS, BB);
    fused_kernel<<<g, TPB>>>(constants, scales, rotations, centers,
                             samples, grid, w2g, out);
}